// round 3
// baseline (speedup 1.0000x reference)
#include <cuda_runtime.h>
#include <cuda_bf16.h>
#include <math.h>
#include <stdint.h>

// Problem dims (fixed by the dataset)
#define BATCH 1024
#define SEQ   512
#define DIM   768

// Scratch (allocation-free rule: __device__ globals)
__device__ float g_pooled[BATCH * DIM];
__device__ float g_hidden[BATCH * DIM];

// ---------------------------------------------------------------------------
// Kernel 1: masked sum pooling (unchanged: 83% DRAM ~ roofline)
// ---------------------------------------------------------------------------
__global__ __launch_bounds__(384) void pool_kernel(
    const float* __restrict__ x,      // [BATCH, SEQ, DIM]
    const int*   __restrict__ mask)   // [BATCH, SEQ]
{
    __shared__ int s_idx[SEQ];
    __shared__ int s_cnt;

    const int b   = blockIdx.x;
    const int tid = threadIdx.x;

    if (tid == 0) s_cnt = 0;
    __syncthreads();

    const int* mrow = mask + (size_t)b * SEQ;
    for (int s = tid; s < SEQ; s += 384) {
        if (mrow[s] != 0) {
            int p = atomicAdd(&s_cnt, 1);
            s_idx[p] = s;
        }
    }
    __syncthreads();

    const int cnt = s_cnt;
    const float2* base = reinterpret_cast<const float2*>(x + (size_t)b * SEQ * DIM);
    const int rs2 = DIM / 2;

    float2 acc; acc.x = 0.f; acc.y = 0.f;

    int i = 0;
    for (; i + 4 <= cnt; i += 4) {
        int s0 = s_idx[i + 0];
        int s1 = s_idx[i + 1];
        int s2 = s_idx[i + 2];
        int s3 = s_idx[i + 3];
        float2 v0 = base[(size_t)s0 * rs2 + tid];
        float2 v1 = base[(size_t)s1 * rs2 + tid];
        float2 v2 = base[(size_t)s2 * rs2 + tid];
        float2 v3 = base[(size_t)s3 * rs2 + tid];
        acc.x += (v0.x + v1.x) + (v2.x + v3.x);
        acc.y += (v0.y + v1.y) + (v2.y + v3.y);
    }
    for (; i < cnt; i++) {
        float2 v = base[(size_t)s_idx[i] * rs2 + tid];
        acc.x += v.x;
        acc.y += v.y;
    }

    reinterpret_cast<float2*>(g_pooled + (size_t)b * DIM)[tid] = acc;
}

// ---------------------------------------------------------------------------
// Kernel 2: C = tanh(A @ B + bias), error-compensated TF32 tensor-core GEMM.
// Split-once-at-load: smem holds (hi,lo) float2 pairs; inner loop = LDS + MMA.
// Register-prefetch pipeline over the K loop (one tile in flight).
// Tiles: BM=128, BN=64, BK=32; 256 threads = 8 warps (4 M x 2 N), warp tile
// 32x32 from m16n8k8 mma (2 M-frags x 4 N-frags x 3 split-MMAs).
// Grid = (768/64, 1024/128) = (12, 8) = 96 blocks -> one balanced wave.
// ---------------------------------------------------------------------------
#define GBM 128
#define GBN 64
#define GBK 32
#define AS2 33   // As2 row stride in float2 (32 k-pairs + 1 pad)
#define BS2 66   // Bs2 row stride in float2 (64 n-pairs + 2 pad)
#define GEMM_SMEM_F2 (GBM * AS2 + GBK * BS2)   // 4224 + 2112 = 6336 float2
#define GEMM_SMEM_BYTES (GEMM_SMEM_F2 * 8)     // 50688 B

__device__ __forceinline__ float2 split_tf32_f2(float x)
{
    uint32_t hb = __float_as_uint(x) & 0xFFFFE000u;
    float hi = __uint_as_float(hb);
    float2 r; r.x = hi; r.y = x - hi;
    return r;
}

__device__ __forceinline__ void mma_tf32(
    float c[4], uint32_t a0, uint32_t a1, uint32_t a2, uint32_t a3,
    uint32_t b0, uint32_t b1)
{
    asm volatile(
        "mma.sync.aligned.m16n8k8.row.col.f32.tf32.tf32.f32 "
        "{%0,%1,%2,%3}, {%4,%5,%6,%7}, {%8,%9}, {%0,%1,%2,%3};\n"
        : "+f"(c[0]), "+f"(c[1]), "+f"(c[2]), "+f"(c[3])
        : "r"(a0), "r"(a1), "r"(a2), "r"(a3), "r"(b0), "r"(b1));
}

__global__ __launch_bounds__(256, 1) void gemm_tf32_bias_tanh(
    const float* __restrict__ A,
    const float* __restrict__ Bm,
    const float* __restrict__ bias,
    float* __restrict__ C,
    int M, int N, int K)
{
    extern __shared__ float2 smem2[];
    float2* As2 = smem2;                 // [GBM][AS2]  (m-major, k inner)
    float2* Bs2 = smem2 + GBM * AS2;     // [GBK][BS2]  (k-major, n inner)

    const int tid  = threadIdx.x;
    const int lane = tid & 31;
    const int warp = tid >> 5;           // 0..7
    const int gid  = lane >> 2;          // 0..7
    const int tig  = lane & 3;           // 0..3
    const int warpM = (warp >> 1) * 32;  // 0,32,64,96
    const int warpN = (warp & 1) * 32;   // 0,32

    const int m0 = blockIdx.y * GBM;
    const int n0 = blockIdx.x * GBN;

    // Global load mapping (fixed per thread)
    const int a_ar = tid >> 3;           // 0..31 (A row group base)
    const int a_ac = (tid & 7) << 2;     // 0..28 (k offset)
    const int b_br = tid >> 4;           // 0..15 (B k-row base)
    const int b_bc = (tid & 15) << 2;    // 0..60 (n offset)

    const float* Abase = A  + (size_t)(m0 + a_ar) * K + a_ac;
    const float* Bbase = Bm + (size_t)b_br * N + n0 + b_bc;

    float acc[2][4][4];
#pragma unroll
    for (int mt = 0; mt < 2; mt++)
#pragma unroll
        for (int nt = 0; nt < 4; nt++)
#pragma unroll
            for (int r = 0; r < 4; r++)
                acc[mt][nt][r] = 0.f;

    float4 pa[4], pb[2];

#define LOAD_TILE(k0)                                                          \
    do {                                                                       \
        _Pragma("unroll")                                                      \
        for (int l = 0; l < 4; l++)                                            \
            pa[l] = *reinterpret_cast<const float4*>(                          \
                Abase + (size_t)(32 * l) * K + (k0));                          \
        _Pragma("unroll")                                                      \
        for (int l = 0; l < 2; l++)                                            \
            pb[l] = *reinterpret_cast<const float4*>(                          \
                Bbase + (size_t)((k0) + 16 * l) * N);                          \
    } while (0)

#define STORE_TILE()                                                           \
    do {                                                                       \
        _Pragma("unroll")                                                      \
        for (int l = 0; l < 4; l++) {                                          \
            float2* dst = &As2[(a_ar + 32 * l) * AS2 + a_ac];                  \
            dst[0] = split_tf32_f2(pa[l].x);                                   \
            dst[1] = split_tf32_f2(pa[l].y);                                   \
            dst[2] = split_tf32_f2(pa[l].z);                                   \
            dst[3] = split_tf32_f2(pa[l].w);                                   \
        }                                                                      \
        _Pragma("unroll")                                                      \
        for (int l = 0; l < 2; l++) {                                          \
            float2* dst = &Bs2[(b_br + 16 * l) * BS2 + b_bc];                  \
            dst[0] = split_tf32_f2(pb[l].x);                                   \
            dst[1] = split_tf32_f2(pb[l].y);                                   \
            dst[2] = split_tf32_f2(pb[l].z);                                   \
            dst[3] = split_tf32_f2(pb[l].w);                                   \
        }                                                                      \
    } while (0)

    LOAD_TILE(0);
    STORE_TILE();
    __syncthreads();

    const int NIT = K / GBK;   // 24
    for (int it = 0; it < NIT; ++it) {
        const bool more = (it + 1 < NIT);
        if (more) LOAD_TILE((it + 1) * GBK);

        // Compute on current smem tile
#pragma unroll
        for (int ks = 0; ks < 4; ks++) {
            const int kb = ks * 8;

            float2 af[2][4];
#pragma unroll
            for (int mt = 0; mt < 2; mt++) {
                const int rm = warpM + mt * 16 + gid;
                af[mt][0] = As2[rm * AS2 + kb + tig];
                af[mt][1] = As2[(rm + 8) * AS2 + kb + tig];
                af[mt][2] = As2[rm * AS2 + kb + tig + 4];
                af[mt][3] = As2[(rm + 8) * AS2 + kb + tig + 4];
            }
            float2 bf[4][2];
#pragma unroll
            for (int nt = 0; nt < 4; nt++) {
                const int nn = warpN + nt * 8 + gid;
                bf[nt][0] = Bs2[(kb + tig) * BS2 + nn];
                bf[nt][1] = Bs2[(kb + tig + 4) * BS2 + nn];
            }

#pragma unroll
            for (int mt = 0; mt < 2; mt++) {
                const uint32_t ah0 = __float_as_uint(af[mt][0].x);
                const uint32_t ah1 = __float_as_uint(af[mt][1].x);
                const uint32_t ah2 = __float_as_uint(af[mt][2].x);
                const uint32_t ah3 = __float_as_uint(af[mt][3].x);
                const uint32_t al0 = __float_as_uint(af[mt][0].y);
                const uint32_t al1 = __float_as_uint(af[mt][1].y);
                const uint32_t al2 = __float_as_uint(af[mt][2].y);
                const uint32_t al3 = __float_as_uint(af[mt][3].y);
#pragma unroll
                for (int nt = 0; nt < 4; nt++) {
                    const uint32_t bh0 = __float_as_uint(bf[nt][0].x);
                    const uint32_t bh1 = __float_as_uint(bf[nt][1].x);
                    const uint32_t bl0 = __float_as_uint(bf[nt][0].y);
                    const uint32_t bl1 = __float_as_uint(bf[nt][1].y);
                    mma_tf32(acc[mt][nt], ah0, ah1, ah2, ah3, bh0, bh1);
                    mma_tf32(acc[mt][nt], ah0, ah1, ah2, ah3, bl0, bl1);
                    mma_tf32(acc[mt][nt], al0, al1, al2, al3, bh0, bh1);
                }
            }
        }

        if (more) {
            __syncthreads();   // all reads of current tile done
            STORE_TILE();      // overwrite with next tile
            __syncthreads();   // tile visible before next compute
        }
    }

    // Epilogue: bias + tanh
#pragma unroll
    for (int mt = 0; mt < 2; mt++) {
#pragma unroll
        for (int nt = 0; nt < 4; nt++) {
            const int row = m0 + warpM + mt * 16 + gid;
            const int col = n0 + warpN + nt * 8 + tig * 2;
            float2 bv = *reinterpret_cast<const float2*>(bias + col);
            float2 o0;
            o0.x = tanhf(acc[mt][nt][0] + bv.x);
            o0.y = tanhf(acc[mt][nt][1] + bv.y);
            *reinterpret_cast<float2*>(C + (size_t)row * N + col) = o0;
            float2 o1;
            o1.x = tanhf(acc[mt][nt][2] + bv.x);
            o1.y = tanhf(acc[mt][nt][3] + bv.y);
            *reinterpret_cast<float2*>(C + (size_t)(row + 8) * N + col) = o1;
        }
    }
#undef LOAD_TILE
#undef STORE_TILE
}

// ---------------------------------------------------------------------------
// Launch
// ---------------------------------------------------------------------------
extern "C" void kernel_launch(void* const* d_in, const int* in_sizes, int n_in,
                              void* d_out, int out_size)
{
    const float* token_embeds = (const float*)d_in[0];
    const int*   attn_mask    = (const int*)  d_in[1];
    const float* W1           = (const float*)d_in[2];
    const float* b1           = (const float*)d_in[3];
    const float* W2           = (const float*)d_in[4];
    const float* b2           = (const float*)d_in[5];
    float*       out          = (float*)d_out;

    float* pooled = nullptr;
    float* hidden = nullptr;
    cudaGetSymbolAddress((void**)&pooled, g_pooled);
    cudaGetSymbolAddress((void**)&hidden, g_hidden);

    cudaFuncSetAttribute(gemm_tf32_bias_tanh,
                         cudaFuncAttributeMaxDynamicSharedMemorySize,
                         GEMM_SMEM_BYTES);

    // 1) masked sum pooling
    pool_kernel<<<BATCH, 384>>>(token_embeds, attn_mask);

    // 2) h = tanh(pooled @ W1 + b1)
    dim3 grid1(DIM / GBN, BATCH / GBM);   // (12, 8) = 96 blocks
    gemm_tf32_bias_tanh<<<grid1, 256, GEMM_SMEM_BYTES>>>(
        pooled, W1, b1, hidden, BATCH, DIM, DIM);

    // 3) out = tanh(h @ W2 + b2)
    gemm_tf32_bias_tanh<<<grid1, 256, GEMM_SMEM_BYTES>>>(
        hidden, W2, b2, out, BATCH, DIM, DIM);
}